// round 4
// baseline (speedup 1.0000x reference)
#include <cuda_runtime.h>
#include <cstdint>
#include <cstddef>
#include <cmath>

#define HDIM    1024
#define GDIM    4096
#define BATCH   64
#define TSTEPS  256
#define NLAYERS 4
#define SWP     1028   // padded W row stride (conflict-free: row*4 mod 32 distinct over 8 rows)

// ---------------- scratch (static __device__ — allocation-free) ----------------
__device__ __align__(256) float g_xp[(size_t)TSTEPS * BATCH * GDIM];   // xp of current layer [T][B][4H]
__device__ __align__(256) float g_hs[(size_t)TSTEPS * BATCH * HDIM];   // h chain / layer output [T][B][H]
__device__ __align__(256) float g_zero_h[BATCH * HDIM];                // stays zero (h_{-1})
__device__ int g_ctr;                                                   // grid barrier counter (reset each replay)

// ---------------- tf32 helpers ----------------
__device__ __forceinline__ uint32_t f2tf(float f) {
    uint32_t r;
    asm("cvt.rna.tf32.f32 %0, %1;" : "=r"(r) : "f"(f));
    return r;
}

__device__ __forceinline__ void mma_tf32(float c[4],
    uint32_t a0, uint32_t a1, uint32_t a2, uint32_t a3,
    uint32_t b0, uint32_t b1)
{
    asm volatile(
        "mma.sync.aligned.m16n8k8.row.col.f32.tf32.tf32.f32 "
        "{%0,%1,%2,%3}, {%4,%5,%6,%7}, {%8,%9}, {%0,%1,%2,%3};\n"
        : "+f"(c[0]), "+f"(c[1]), "+f"(c[2]), "+f"(c[3])
        : "r"(a0), "r"(a1), "r"(a2), "r"(a3), "r"(b0), "r"(b1));
}

// ---------------------------------------------------------------------------
__global__ void reset_kernel() { g_ctr = 0; }

// ---------------------------------------------------------------------------
// Layer-0 input projection: xp[t][b][g] = x[b][t][0]*w0[g][0]+x[b][t][1]*w0[g][1]+bias
// ---------------------------------------------------------------------------
__global__ void layer0_xp_kernel(const float* __restrict__ x, const float* __restrict__ w0,
                                 const float* __restrict__ bih, const float* __restrict__ bhh)
{
    const int idx = blockIdx.x * 256 + threadIdx.x;
    const int g = idx & (GDIM - 1);
    const int m = idx >> 12;           // t*64 + b
    const int t = m >> 6;
    const int b = m & 63;
    const float x0 = x[(b * TSTEPS + t) * 2 + 0];
    const float x1 = x[(b * TSTEPS + t) * 2 + 1];
    g_xp[idx] = x0 * w0[2 * g] + x1 * w0[2 * g + 1] + bih[g] + bhh[g];
}

// ---------------------------------------------------------------------------
// Input projection layers 1..3: g_xp = g_hs @ w_ih^T + (b_ih+b_hh)
// 64x64 tile per CTA. grid = (64 n-blocks, 256 m-blocks), 256 threads (8 warps,
// warp tile 16x32 as 4x m16n8k8 per k-step).
// ---------------------------------------------------------------------------
__global__ __launch_bounds__(256) void proj64_kernel(
    const float* __restrict__ wih,
    const float* __restrict__ bih,
    const float* __restrict__ bhh)
{
    __shared__ uint32_t sA[64 * 36];
    __shared__ uint32_t sB[64 * 36];

    const int nb = blockIdx.x;   // 0..63
    const int mb = blockIdx.y;   // 0..255

    const float* A  = g_hs + (size_t)mb * 64 * HDIM;
    const float* Bm = wih  + (size_t)nb * 64 * HDIM;

    const int tid  = threadIdx.x;
    const int lane = tid & 31;
    const int wp   = tid >> 5;
    const int mrow = (wp >> 1) * 16;   // warp m-row (4 rows of warps)
    const int nbase = (wp & 1) * 32;   // warp n-col (2 cols of warps)
    const int gid  = lane >> 2;
    const int tig  = lane & 3;

    const int ar = tid >> 3;           // 0..31
    const int ac = (tid & 7) * 4;

    const float* ap0 = A  + (size_t)ar        * HDIM + ac;
    const float* ap1 = A  + (size_t)(ar + 32) * HDIM + ac;
    const float* bp0 = Bm + (size_t)ar        * HDIM + ac;
    const float* bp1 = Bm + (size_t)(ar + 32) * HDIM + ac;

    float4 ra0 = *reinterpret_cast<const float4*>(ap0);
    float4 ra1 = *reinterpret_cast<const float4*>(ap1);
    float4 rb0 = *reinterpret_cast<const float4*>(bp0);
    float4 rb1 = *reinterpret_cast<const float4*>(bp1);

    float acc[4][4] = {};

    for (int kc = 0; kc < HDIM; kc += 32) {
        *reinterpret_cast<uint4*>(&sA[ar * 36 + ac]) =
            make_uint4(f2tf(ra0.x), f2tf(ra0.y), f2tf(ra0.z), f2tf(ra0.w));
        *reinterpret_cast<uint4*>(&sA[(ar + 32) * 36 + ac]) =
            make_uint4(f2tf(ra1.x), f2tf(ra1.y), f2tf(ra1.z), f2tf(ra1.w));
        *reinterpret_cast<uint4*>(&sB[ar * 36 + ac]) =
            make_uint4(f2tf(rb0.x), f2tf(rb0.y), f2tf(rb0.z), f2tf(rb0.w));
        *reinterpret_cast<uint4*>(&sB[(ar + 32) * 36 + ac]) =
            make_uint4(f2tf(rb1.x), f2tf(rb1.y), f2tf(rb1.z), f2tf(rb1.w));
        __syncthreads();
        if (kc + 32 < HDIM) {
            ra0 = *reinterpret_cast<const float4*>(ap0 + kc + 32);
            ra1 = *reinterpret_cast<const float4*>(ap1 + kc + 32);
            rb0 = *reinterpret_cast<const float4*>(bp0 + kc + 32);
            rb1 = *reinterpret_cast<const float4*>(bp1 + kc + 32);
        }
        #pragma unroll
        for (int ki = 0; ki < 4; ki++) {
            const int k0 = ki * 8 + tig;
            uint32_t a0 = sA[(mrow + gid)     * 36 + k0];
            uint32_t a1 = sA[(mrow + gid + 8) * 36 + k0];
            uint32_t a2 = sA[(mrow + gid)     * 36 + k0 + 4];
            uint32_t a3 = sA[(mrow + gid + 8) * 36 + k0 + 4];
            #pragma unroll
            for (int nt = 0; nt < 4; nt++) {
                const int nbr = nbase + nt * 8 + gid;
                uint32_t b0 = sB[nbr * 36 + k0];
                uint32_t b1 = sB[nbr * 36 + k0 + 4];
                mma_tf32(acc[nt], a0, a1, a2, a3, b0, b1);
            }
        }
        __syncthreads();
    }

    const int r0 = mrow + gid, r1 = r0 + 8;
    #pragma unroll
    for (int nt = 0; nt < 4; nt++) {
        const int c = nbase + nt * 8 + tig * 2;
        const int n = nb * 64 + c;
        const float b0v = bih[n] + bhh[n];
        const float b1v = bih[n + 1] + bhh[n + 1];
        float* o0 = g_xp + ((size_t)mb * 64 + r0) * GDIM + n;
        float* o1 = g_xp + ((size_t)mb * 64 + r1) * GDIM + n;
        o0[0] = acc[nt][0] + b0v;
        o0[1] = acc[nt][1] + b1v;
        o1[0] = acc[nt][2] + b0v;
        o1[1] = acc[nt][3] + b1v;
    }
}

// ---------------------------------------------------------------------------
// Persistent LSTM layer kernel: 128 CTAs x 256 threads, all 256 timesteps.
// CTA u owns hidden units [u*8, u*8+8) — all 4 gate types (32 W_hh rows,
// ordered [i0..i7, f0..f7, g0..g7, o0..o7]) held tf32-converted in SMEM for
// the whole layer. Cell state c lives in SMEM. Grid barrier between steps
// via monotonic L2 counter g_ctr.
// ---------------------------------------------------------------------------
__global__ __launch_bounds__(256, 1) void lstm_layer_kernel(
    const float* __restrict__ whh, int step_base /* layer*TSTEPS */)
{
    extern __shared__ uint32_t sh[];
    uint32_t* sW = sh;                           // 32 * SWP
    uint32_t* sA = sW + 32 * SWP;                // 64 * 36
    float*    sG = (float*)(sA + 64 * 36);       // 64 * 33 gate tile
    float*    sC = sG + 64 * 33;                 // 512 cell states

    const int tid = threadIdx.x;
    const int u   = blockIdx.x;                  // 0..127

    // Load + convert this CTA's 32 gathered W_hh rows into SMEM (once per layer).
    for (int idx = tid; idx < 32 * HDIM; idx += 256) {
        const int r = idx >> 10, k = idx & (HDIM - 1);
        const int tau = r >> 3, j = r & 7;
        const float v = whh[((size_t)(tau * HDIM + u * 8 + j)) * HDIM + k];
        sW[r * SWP + k] = f2tf(v);
    }
    for (int i = tid; i < 512; i += 256) sC[i] = 0.f;
    __syncthreads();

    const int lane = tid & 31, wp = tid >> 5;
    const int mrow = (wp >> 1) * 16;
    const int ncol = (wp & 1) * 16;
    const int gid  = lane >> 2, tig = lane & 3;
    const int ar   = tid >> 3, ac = (tid & 7) * 4;

    for (int t = 0; t < TSTEPS; t++) {
        const float* h_prev = (t == 0) ? g_zero_h
                                       : g_hs + (size_t)(t - 1) * (BATCH * HDIM);
        const float* xp_t = g_xp + (size_t)t * (BATCH * GDIM);

        const float* ap0 = h_prev + (size_t)ar        * HDIM + ac;
        const float* ap1 = h_prev + (size_t)(ar + 32) * HDIM + ac;
        float4 ra0 = *reinterpret_cast<const float4*>(ap0);
        float4 ra1 = *reinterpret_cast<const float4*>(ap1);

        float acc[2][4] = {};

        for (int kc = 0; kc < HDIM; kc += 32) {
            *reinterpret_cast<uint4*>(&sA[ar * 36 + ac]) =
                make_uint4(f2tf(ra0.x), f2tf(ra0.y), f2tf(ra0.z), f2tf(ra0.w));
            *reinterpret_cast<uint4*>(&sA[(ar + 32) * 36 + ac]) =
                make_uint4(f2tf(ra1.x), f2tf(ra1.y), f2tf(ra1.z), f2tf(ra1.w));
            __syncthreads();
            if (kc + 32 < HDIM) {
                ra0 = *reinterpret_cast<const float4*>(ap0 + kc + 32);
                ra1 = *reinterpret_cast<const float4*>(ap1 + kc + 32);
            }
            #pragma unroll
            for (int ki = 0; ki < 4; ki++) {
                const int k0 = ki * 8 + tig;
                uint32_t a0 = sA[(mrow + gid)     * 36 + k0];
                uint32_t a1 = sA[(mrow + gid + 8) * 36 + k0];
                uint32_t a2 = sA[(mrow + gid)     * 36 + k0 + 4];
                uint32_t a3 = sA[(mrow + gid + 8) * 36 + k0 + 4];
                #pragma unroll
                for (int nt = 0; nt < 2; nt++) {
                    const int nbr = ncol + nt * 8 + gid;
                    uint32_t b0 = sW[nbr * SWP + kc + k0];
                    uint32_t b1 = sW[nbr * SWP + kc + k0 + 4];
                    mma_tf32(acc[nt], a0, a1, a2, a3, b0, b1);
                }
            }
            __syncthreads();
        }

        // gates (+xp) -> sG.  col c: type tau = c>>3, unit j = c&7 (c even, so
        // c and c+1 share tau).
        const int r0 = mrow + gid, r1 = r0 + 8;
        #pragma unroll
        for (int nt = 0; nt < 2; nt++) {
            const int c   = ncol + nt * 8 + tig * 2;
            const int tau = c >> 3;
            const int colg = tau * HDIM + u * 8 + (c & 7);   // column in xp
            sG[r0 * 33 + c]     = acc[nt][0] + xp_t[(size_t)r0 * GDIM + colg];
            sG[r0 * 33 + c + 1] = acc[nt][1] + xp_t[(size_t)r0 * GDIM + colg + 1];
            sG[r1 * 33 + c]     = acc[nt][2] + xp_t[(size_t)r1 * GDIM + colg];
            sG[r1 * 33 + c + 1] = acc[nt][3] + xp_t[(size_t)r1 * GDIM + colg + 1];
        }
        __syncthreads();

        // CTA-local elementwise update for 64 batches x 8 units.
        float* hs_out = g_hs + (size_t)t * (BATCH * HDIM);
        #pragma unroll
        for (int e = tid; e < 512; e += 256) {
            const int b = e >> 3, j = e & 7;
            float iv = sG[b * 33 + j];
            float fv = sG[b * 33 + 8 + j];
            float gv = sG[b * 33 + 16 + j];
            float ov = sG[b * 33 + 24 + j];
            iv = 1.f / (1.f + expf(-iv));
            fv = 1.f / (1.f + expf(-fv));
            gv = tanhf(gv);
            ov = 1.f / (1.f + expf(-ov));
            const float cn = fv * sC[e] + iv * gv;
            sC[e] = cn;
            hs_out[b * HDIM + u * 8 + j] = ov * tanhf(cn);
        }

        // grid barrier: release h_t, then wait for all 128 CTAs.
        __threadfence();
        __syncthreads();
        if (tid == 0) {
            atomicAdd(&g_ctr, 1);
            const int target = 128 * (step_base + t + 1);
            while (atomicAdd(&g_ctr, 0) < target) __nanosleep(32);
        }
        __syncthreads();
    }
}

// ---------------------------------------------------------------------------
__global__ void fc_kernel(const float* __restrict__ fc_w, const float* __restrict__ fc_b,
                          float* __restrict__ out)
{
    const int b = blockIdx.x;
    const float* h = g_hs + (size_t)(TSTEPS - 1) * (BATCH * HDIM) + (size_t)b * HDIM;
    float s = 0.f;
    for (int k = threadIdx.x; k < HDIM; k += 256) s += h[k] * fc_w[k];
    #pragma unroll
    for (int o = 16; o > 0; o >>= 1) s += __shfl_down_sync(0xffffffffu, s, o);
    __shared__ float red[8];
    if ((threadIdx.x & 31) == 0) red[threadIdx.x >> 5] = s;
    __syncthreads();
    if (threadIdx.x == 0) {
        float v = 0.f;
        #pragma unroll
        for (int i = 0; i < 8; i++) v += red[i];
        out[b] = v + fc_b[0];
    }
}

// ---------------------------------------------------------------------------
extern "C" void kernel_launch(void* const* d_in, const int* in_sizes, int n_in,
                              void* d_out, int out_size)
{
    (void)in_sizes; (void)n_in; (void)out_size;
    const float* x      = (const float*)d_in[0];
    const float* w_ih0  = (const float*)d_in[1];
    const float* w_rest = (const float*)d_in[2];
    const float* w_hh   = (const float*)d_in[3];
    const float* b_ih   = (const float*)d_in[4];
    const float* b_hh   = (const float*)d_in[5];
    const float* fc_w   = (const float*)d_in[6];
    const float* fc_b   = (const float*)d_in[7];
    float* out = (float*)d_out;

    const int lstm_smem = (32 * SWP + 64 * 36) * 4 + (64 * 33 + 512) * 4;  // 151,296 B
    static bool attr_set = false;
    if (!attr_set) {
        cudaFuncSetAttribute(lstm_layer_kernel,
                             cudaFuncAttributeMaxDynamicSharedMemorySize, lstm_smem);
        attr_set = true;
    }

    reset_kernel<<<1, 1>>>();

    layer0_xp_kernel<<<(TSTEPS * BATCH * GDIM) / 256, 256>>>(x, w_ih0, b_ih, b_hh);

    for (int l = 0; l < NLAYERS; l++) {
        if (l > 0) {
            proj64_kernel<<<dim3(64, 256), 256>>>(
                w_rest + (size_t)(l - 1) * GDIM * HDIM,
                b_ih + (size_t)l * GDIM,
                b_hh + (size_t)l * GDIM);
        }
        lstm_layer_kernel<<<128, 256, lstm_smem>>>(
            w_hh + (size_t)l * GDIM * HDIM, l * TSTEPS);
    }

    fc_kernel<<<BATCH, 256>>>(fc_w, fc_b, out);
}